// round 3
// baseline (speedup 1.0000x reference)
#include <cuda_runtime.h>

#define B_    4
#define N1_   2048
#define N2_   8192
#define C1_   256
#define C2_   128
#define INCH  384
#define OUTCH 256

// Scratch (allocation-free rule: __device__ globals, referenced directly
// from device code — no host-side symbol lookups needed).
__device__ float g_X[B_ * N2_ * INCH];    // 48 MB: [interp | pts2] concat
__device__ float g_Y1[B_ * N2_ * OUTCH];  // 32 MB: layer-1 output

// ---------------------------------------------------------------------------
// Kernel 1: KNN (K=3) + inverse-distance interpolation + concat -> g_X
// One warp per query point. xyz1 of this batch staged in SMEM as float4.
// ---------------------------------------------------------------------------
__global__ __launch_bounds__(256) void knn_interp_kernel(
    const float* __restrict__ xyz1, const float* __restrict__ xyz2,
    const float* __restrict__ pts1, const float* __restrict__ pts2)
{
    __shared__ float4 sp[N1_];
    const int b   = blockIdx.y;
    const int tid = threadIdx.x;

    const float* x1 = xyz1 + (size_t)b * N1_ * 3;
    for (int p = tid; p < N1_; p += 256)
        sp[p] = make_float4(x1[3*p], x1[3*p+1], x1[3*p+2], 0.f);
    __syncthreads();

    const int lane = tid & 31;
    const int q    = blockIdx.x * 8 + (tid >> 5);
    const int row  = b * N2_ + q;

    const float qx = xyz2[row*3+0];
    const float qy = xyz2[row*3+1];
    const float qz = xyz2[row*3+2];

    // per-lane top-3 (sorted ascending)
    float t0 = 3.4e38f, t1 = 3.4e38f, t2 = 3.4e38f;
    int   i0 = 0, i1 = 0, i2 = 0;

    #pragma unroll 4
    for (int i = lane; i < N1_; i += 32) {
        float4 p = sp[i];
        float dx = p.x - qx, dy = p.y - qy, dz = p.z - qz;
        float d = dx*dx + dy*dy + dz*dz;
        if (d < t2) {
            if (d < t1) {
                t2 = t1; i2 = i1;
                if (d < t0) { t1 = t0; i1 = i0; t0 = d; i0 = i; }
                else        { t1 = d;  i1 = i; }
            } else { t2 = d; i2 = i; }
        }
    }

    // merge top-3 across the warp: 3 rounds of arg-min over each lane's head
    int head = 0;
    float selD[3]; int selI[3];
    #pragma unroll
    for (int r = 0; r < 3; ++r) {
        float cd  = (head == 0) ? t0 : (head == 1) ? t1 : (head == 2) ? t2 : 3.4e38f;
        int   ci  = (head == 0) ? i0 : (head == 1) ? i1 : (head == 2) ? i2 : 0;
        float bestD = cd; int bestLane = lane;
        #pragma unroll
        for (int off = 16; off; off >>= 1) {
            float od = __shfl_xor_sync(0xffffffffu, bestD, off);
            int   ol = __shfl_xor_sync(0xffffffffu, bestLane, off);
            if (od < bestD || (od == bestD && ol < bestLane)) { bestD = od; bestLane = ol; }
        }
        selD[r] = bestD;
        selI[r] = __shfl_sync(0xffffffffu, ci, bestLane);
        if (lane == bestLane) head++;
    }

    float d0 = fmaxf(selD[0], 1e-10f);
    float d1 = fmaxf(selD[1], 1e-10f);
    float d2 = fmaxf(selD[2], 1e-10f);
    float w0 = 1.f / (d0 + 1e-8f);
    float w1 = 1.f / (d1 + 1e-8f);
    float w2 = 1.f / (d2 + 1e-8f);
    float inv = 1.f / (w0 + w1 + w2);
    w0 *= inv; w1 *= inv; w2 *= inv;

    const float* p0 = pts1 + (size_t)(b * N1_ + selI[0]) * C1_;
    const float* p1 = pts1 + (size_t)(b * N1_ + selI[1]) * C1_;
    const float* p2 = pts1 + (size_t)(b * N1_ + selI[2]) * C1_;
    float* xr = g_X + (size_t)row * INCH;

    for (int c = lane; c < C1_; c += 32)
        xr[c] = w0 * p0[c] + w1 * p1[c] + w2 * p2[c];

    const float* pq = pts2 + (size_t)row * C2_;
    for (int c = lane; c < C2_; c += 32)
        xr[C1_ + c] = pq[c];
}

// ---------------------------------------------------------------------------
// Kernel 2/3: C = relu(BN(A @ W + bias))   (BN eval-mode folded into epilogue)
// M=32768, N=256 fixed; K is 384 or 256. 128x128 tile, BK=8, double-buffered,
// 256 threads, 8x8 per thread in a 4+4 quadrant split (conflict-free LDS.128,
// fully coalesced float4 stores).
// ---------------------------------------------------------------------------
__global__ __launch_bounds__(256) void sgemm_bn_relu(
    const float* __restrict__ A, const float* __restrict__ W,
    const float* __restrict__ bias, const float* __restrict__ gamma,
    const float* __restrict__ beta, const float* __restrict__ rmean,
    const float* __restrict__ rvar, float* __restrict__ C, int K)
{
    const int N = OUTCH;
    __shared__ float As[2][8][128];
    __shared__ float Bs[2][8][128];

    const int tid = threadIdx.x;
    const int m0  = blockIdx.y * 128;
    const int n0  = blockIdx.x * 128;
    const int tm  = tid >> 4;        // 0..15
    const int tn  = tid & 15;        // 0..15

    const int arow = tid >> 1;       // 0..127
    const int acol = (tid & 1) * 4;  // 0 or 4
    const int brow = tid >> 5;       // 0..7
    const int bcol = (tid & 31) * 4; // 0..124

    const float* Ag = A + (size_t)(m0 + arow) * K + acol;
    const float* Wg = W + (size_t)brow * N + n0 + bcol;

    float acc[8][8];
    #pragma unroll
    for (int i = 0; i < 8; ++i)
        #pragma unroll
        for (int j = 0; j < 8; ++j) acc[i][j] = 0.f;

    const int nk = K >> 3;
    {
        float4 av = *(const float4*)Ag;
        As[0][acol  ][arow] = av.x; As[0][acol+1][arow] = av.y;
        As[0][acol+2][arow] = av.z; As[0][acol+3][arow] = av.w;
        *(float4*)&Bs[0][brow][bcol] = *(const float4*)Wg;
    }
    __syncthreads();

    for (int kt = 0; kt < nk; ++kt) {
        const int buf = kt & 1;
        float4 av, bv;
        const bool pf = (kt + 1 < nk);
        if (pf) {
            av = *(const float4*)(Ag + (kt + 1) * 8);
            bv = *(const float4*)(Wg + (size_t)(kt + 1) * 8 * N);
        }
        #pragma unroll
        for (int k = 0; k < 8; ++k) {
            float a[8], bb[8];
            *(float4*)&a[0]  = *(const float4*)&As[buf][k][tm * 4];
            *(float4*)&a[4]  = *(const float4*)&As[buf][k][64 + tm * 4];
            *(float4*)&bb[0] = *(const float4*)&Bs[buf][k][tn * 4];
            *(float4*)&bb[4] = *(const float4*)&Bs[buf][k][64 + tn * 4];
            #pragma unroll
            for (int i = 0; i < 8; ++i)
                #pragma unroll
                for (int j = 0; j < 8; ++j)
                    acc[i][j] = fmaf(a[i], bb[j], acc[i][j]);
        }
        if (pf) {
            const int nb = buf ^ 1;
            As[nb][acol  ][arow] = av.x; As[nb][acol+1][arow] = av.y;
            As[nb][acol+2][arow] = av.z; As[nb][acol+3][arow] = av.w;
            *(float4*)&Bs[nb][brow][bcol] = bv;
        }
        __syncthreads();
    }

    // Fused epilogue: y = relu(acc * s + sh), s = g*rsqrt(rv+eps),
    // sh = (bias - rm)*s + be
    float s[8], sh[8];
    #pragma unroll
    for (int j = 0; j < 8; ++j) {
        int col  = n0 + ((j < 4) ? tn * 4 + j : 64 + tn * 4 + (j - 4));
        float sc = gamma[col] * rsqrtf(rvar[col] + 1e-5f);
        s[j]  = sc;
        sh[j] = (bias[col] - rmean[col]) * sc + beta[col];
    }
    #pragma unroll
    for (int i = 0; i < 8; ++i) {
        int m = m0 + ((i < 4) ? tm * 4 + i : 64 + tm * 4 + (i - 4));
        float4 v0, v1;
        v0.x = fmaxf(acc[i][0]*s[0] + sh[0], 0.f);
        v0.y = fmaxf(acc[i][1]*s[1] + sh[1], 0.f);
        v0.z = fmaxf(acc[i][2]*s[2] + sh[2], 0.f);
        v0.w = fmaxf(acc[i][3]*s[3] + sh[3], 0.f);
        v1.x = fmaxf(acc[i][4]*s[4] + sh[4], 0.f);
        v1.y = fmaxf(acc[i][5]*s[5] + sh[5], 0.f);
        v1.z = fmaxf(acc[i][6]*s[6] + sh[6], 0.f);
        v1.w = fmaxf(acc[i][7]*s[7] + sh[7], 0.f);
        float* cp = C + (size_t)m * N + n0;
        *(float4*)(cp + tn * 4)      = v0;
        *(float4*)(cp + 64 + tn * 4) = v1;
    }
}

// Thin wrappers so the GEMMs can name the __device__ scratch directly
// (keeps kernel_launch to pure kernel launches — maximally capture-safe).
__global__ __launch_bounds__(256) void sgemm1_wrap(
    const float* __restrict__ W, const float* __restrict__ bias,
    const float* __restrict__ gamma, const float* __restrict__ beta,
    const float* __restrict__ rmean, const float* __restrict__ rvar);
__global__ __launch_bounds__(256) void sgemm2_wrap(
    const float* __restrict__ W, const float* __restrict__ bias,
    const float* __restrict__ gamma, const float* __restrict__ beta,
    const float* __restrict__ rmean, const float* __restrict__ rvar,
    float* __restrict__ C);

// ---------------------------------------------------------------------------
extern "C" void kernel_launch(void* const* d_in, const int* in_sizes, int n_in,
                              void* d_out, int out_size)
{
    const float* xyz1 = (const float*)d_in[0];
    const float* xyz2 = (const float*)d_in[1];
    const float* pts1 = (const float*)d_in[2];
    const float* pts2 = (const float*)d_in[3];
    const float* W1   = (const float*)d_in[4];
    const float* b1   = (const float*)d_in[5];
    const float* g1   = (const float*)d_in[6];
    const float* be1  = (const float*)d_in[7];
    const float* rm1  = (const float*)d_in[8];
    const float* rv1  = (const float*)d_in[9];
    const float* W2   = (const float*)d_in[10];
    const float* b2   = (const float*)d_in[11];
    const float* g2   = (const float*)d_in[12];
    const float* be2  = (const float*)d_in[13];
    const float* rm2  = (const float*)d_in[14];
    const float* rv2  = (const float*)d_in[15];
    float* out = (float*)d_out;

    knn_interp_kernel<<<dim3(N2_ / 8, B_), 256>>>(xyz1, xyz2, pts1, pts2);
    sgemm1_wrap<<<dim3(2, 256), 256>>>(W1, b1, g1, be1, rm1, rv1);
    sgemm2_wrap<<<dim3(2, 256), 256>>>(W2, b2, g2, be2, rm2, rv2, out);
}

// Wrapper definitions (after kernel_launch for clarity; forward-declared above).
__global__ __launch_bounds__(256) void sgemm1_wrap(
    const float* __restrict__ W, const float* __restrict__ bias,
    const float* __restrict__ gamma, const float* __restrict__ beta,
    const float* __restrict__ rmean, const float* __restrict__ rvar)
{
    // Delegate by inlining the same body via a device function would duplicate
    // code; instead just call the main kernel's logic with global scratch.
    // We re-implement as a call into sgemm_bn_relu's code path by jumping to
    // it directly is not possible; so replicate minimal: call device-side.
    // Simplest: this wrapper IS the gemm with A=g_X, C=g_Y1, K=INCH.
    extern __shared__ float smem_dummy[]; // (unused; keeps signature simple)
    // --- inline body ---
    const int K = INCH;
    const int N = OUTCH;
    __shared__ float As[2][8][128];
    __shared__ float Bs[2][8][128];
    const float* A = g_X;
    float* C = g_Y1;

    const int tid = threadIdx.x;
    const int m0  = blockIdx.y * 128;
    const int n0  = blockIdx.x * 128;
    const int tm  = tid >> 4;
    const int tn  = tid & 15;
    const int arow = tid >> 1;
    const int acol = (tid & 1) * 4;
    const int brow = tid >> 5;
    const int bcol = (tid & 31) * 4;

    const float* Ag = A + (size_t)(m0 + arow) * K + acol;
    const float* Wg = W + (size_t)brow * N + n0 + bcol;

    float acc[8][8];
    #pragma unroll
    for (int i = 0; i < 8; ++i)
        #pragma unroll
        for (int j = 0; j < 8; ++j) acc[i][j] = 0.f;

    const int nk = K >> 3;
    {
        float4 av = *(const float4*)Ag;
        As[0][acol  ][arow] = av.x; As[0][acol+1][arow] = av.y;
        As[0][acol+2][arow] = av.z; As[0][acol+3][arow] = av.w;
        *(float4*)&Bs[0][brow][bcol] = *(const float4*)Wg;
    }
    __syncthreads();

    for (int kt = 0; kt < nk; ++kt) {
        const int buf = kt & 1;
        float4 av, bv;
        const bool pf = (kt + 1 < nk);
        if (pf) {
            av = *(const float4*)(Ag + (kt + 1) * 8);
            bv = *(const float4*)(Wg + (size_t)(kt + 1) * 8 * N);
        }
        #pragma unroll
        for (int k = 0; k < 8; ++k) {
            float a[8], bb[8];
            *(float4*)&a[0]  = *(const float4*)&As[buf][k][tm * 4];
            *(float4*)&a[4]  = *(const float4*)&As[buf][k][64 + tm * 4];
            *(float4*)&bb[0] = *(const float4*)&Bs[buf][k][tn * 4];
            *(float4*)&bb[4] = *(const float4*)&Bs[buf][k][64 + tn * 4];
            #pragma unroll
            for (int i = 0; i < 8; ++i)
                #pragma unroll
                for (int j = 0; j < 8; ++j)
                    acc[i][j] = fmaf(a[i], bb[j], acc[i][j]);
        }
        if (pf) {
            const int nb = buf ^ 1;
            As[nb][acol  ][arow] = av.x; As[nb][acol+1][arow] = av.y;
            As[nb][acol+2][arow] = av.z; As[nb][acol+3][arow] = av.w;
            *(float4*)&Bs[nb][brow][bcol] = bv;
        }
        __syncthreads();
    }

    float s[8], sh[8];
    #pragma unroll
    for (int j = 0; j < 8; ++j) {
        int col  = n0 + ((j < 4) ? tn * 4 + j : 64 + tn * 4 + (j - 4));
        float sc = gamma[col] * rsqrtf(rvar[col] + 1e-5f);
        s[j]  = sc;
        sh[j] = (bias[col] - rmean[col]) * sc + beta[col];
    }
    #pragma unroll
    for (int i = 0; i < 8; ++i) {
        int m = m0 + ((i < 4) ? tm * 4 + i : 64 + tm * 4 + (i - 4));
        float4 v0, v1;
        v0.x = fmaxf(acc[i][0]*s[0] + sh[0], 0.f);
        v0.y = fmaxf(acc[i][1]*s[1] + sh[1], 0.f);
        v0.z = fmaxf(acc[i][2]*s[2] + sh[2], 0.f);
        v0.w = fmaxf(acc[i][3]*s[3] + sh[3], 0.f);
        v1.x = fmaxf(acc[i][4]*s[4] + sh[4], 0.f);
        v1.y = fmaxf(acc[i][5]*s[5] + sh[5], 0.f);
        v1.z = fmaxf(acc[i][6]*s[6] + sh[6], 0.f);
        v1.w = fmaxf(acc[i][7]*s[7] + sh[7], 0.f);
        float* cp = C + (size_t)m * N + n0;
        *(float4*)(cp + tn * 4)      = v0;
        *(float4*)(cp + 64 + tn * 4) = v1;
    }
}

__global__ __launch_bounds__(256) void sgemm2_wrap(
    const float* __restrict__ W, const float* __restrict__ bias,
    const float* __restrict__ gamma, const float* __restrict__ beta,
    const float* __restrict__ rmean, const float* __restrict__ rvar,
    float* __restrict__ C)
{
    const int K = OUTCH;
    const int N = OUTCH;
    __shared__ float As[2][8][128];
    __shared__ float Bs[2][8][128];
    const float* A = g_Y1;

    const int tid = threadIdx.x;
    const int m0  = blockIdx.y * 128;
    const int n0  = blockIdx.x * 128;
    const int tm  = tid >> 4;
    const int tn  = tid & 15;
    const int arow = tid >> 1;
    const int acol = (tid & 1) * 4;
    const int brow = tid >> 5;
    const int bcol = (tid & 31) * 4;

    const float* Ag = A + (size_t)(m0 + arow) * K + acol;
    const float* Wg = W + (size_t)brow * N + n0 + bcol;

    float acc[8][8];
    #pragma unroll
    for (int i = 0; i < 8; ++i)
        #pragma unroll
        for (int j = 0; j < 8; ++j) acc[i][j] = 0.f;

    const int nk = K >> 3;
    {
        float4 av = *(const float4*)Ag;
        As[0][acol  ][arow] = av.x; As[0][acol+1][arow] = av.y;
        As[0][acol+2][arow] = av.z; As[0][acol+3][arow] = av.w;
        *(float4*)&Bs[0][brow][bcol] = *(const float4*)Wg;
    }
    __syncthreads();

    for (int kt = 0; kt < nk; ++kt) {
        const int buf = kt & 1;
        float4 av, bv;
        const bool pf = (kt + 1 < nk);
        if (pf) {
            av = *(const float4*)(Ag + (kt + 1) * 8);
            bv = *(const float4*)(Wg + (size_t)(kt + 1) * 8 * N);
        }
        #pragma unroll
        for (int k = 0; k < 8; ++k) {
            float a[8], bb[8];
            *(float4*)&a[0]  = *(const float4*)&As[buf][k][tm * 4];
            *(float4*)&a[4]  = *(const float4*)&As[buf][k][64 + tm * 4];
            *(float4*)&bb[0] = *(const float4*)&Bs[buf][k][tn * 4];
            *(float4*)&bb[4] = *(const float4*)&Bs[buf][k][64 + tn * 4];
            #pragma unroll
            for (int i = 0; i < 8; ++i)
                #pragma unroll
                for (int j = 0; j < 8; ++j)
                    acc[i][j] = fmaf(a[i], bb[j], acc[i][j]);
        }
        if (pf) {
            const int nb = buf ^ 1;
            As[nb][acol  ][arow] = av.x; As[nb][acol+1][arow] = av.y;
            As[nb][acol+2][arow] = av.z; As[nb][acol+3][arow] = av.w;
            *(float4*)&Bs[nb][brow][bcol] = bv;
        }
        __syncthreads();
    }

    float s[8], sh[8];
    #pragma unroll
    for (int j = 0; j < 8; ++j) {
        int col  = n0 + ((j < 4) ? tn * 4 + j : 64 + tn * 4 + (j - 4));
        float sc = gamma[col] * rsqrtf(rvar[col] + 1e-5f);
        s[j]  = sc;
        sh[j] = (bias[col] - rmean[col]) * sc + beta[col];
    }
    #pragma unroll
    for (int i = 0; i < 8; ++i) {
        int m = m0 + ((i < 4) ? tm * 4 + i : 64 + tm * 4 + (i - 4));
        float4 v0, v1;
        v0.x = fmaxf(acc[i][0]*s[0] + sh[0], 0.f);
        v0.y = fmaxf(acc[i][1]*s[1] + sh[1], 0.f);
        v0.z = fmaxf(acc[i][2]*s[2] + sh[2], 0.f);
        v0.w = fmaxf(acc[i][3]*s[3] + sh[3], 0.f);
        v1.x = fmaxf(acc[i][4]*s[4] + sh[4], 0.f);
        v1.y = fmaxf(acc[i][5]*s[5] + sh[5], 0.f);
        v1.z = fmaxf(acc[i][6]*s[6] + sh[6], 0.f);
        v1.w = fmaxf(acc[i][7]*s[7] + sh[7], 0.f);
        float* cp = C + (size_t)m * N + n0;
        *(float4*)(cp + tn * 4)      = v0;
        *(float4*)(cp + 64 + tn * 4) = v1;
    }
}

// round 4
// speedup vs baseline: 1.5389x; 1.5389x over previous
#include <cuda_runtime.h>
#include <cstdint>

#define B_    4
#define N1_   2048
#define N2_   8192
#define C1_   256
#define C2_   128
#define INCH  384
#define OUTCH 256
#define BKQ   16      // k-depth per GEMM stage
#define SPAD  136     // smem row stride (mod 32 == 8 -> conflict-free frags)

// Scratch (allocation-free rule: __device__ globals)
__device__ float g_X[B_ * N2_ * INCH];    // 48 MB: [interp | pts2] concat
__device__ float g_Y1[B_ * N2_ * OUTCH];  // 32 MB: layer-1 output

// ---------------------------------------------------------------------------
// Kernel 1: KNN (K=3) + inverse-distance interpolation + concat -> g_X
// One warp per query. xyz1 staged in SMEM as (x,y,z,|p|^2); inner loop
// compares d' = |p|^2 - 2 q.p (3 FFMA), true distance recovered post-merge.
// ---------------------------------------------------------------------------
__global__ __launch_bounds__(256) void knn_interp_kernel(
    const float* __restrict__ xyz1, const float* __restrict__ xyz2,
    const float* __restrict__ pts1, const float* __restrict__ pts2)
{
    __shared__ float4 sp[N1_];
    const int b   = blockIdx.y;
    const int tid = threadIdx.x;

    const float* x1 = xyz1 + (size_t)b * N1_ * 3;
    for (int p = tid; p < N1_; p += 256) {
        float x = x1[3*p], y = x1[3*p+1], z = x1[3*p+2];
        sp[p] = make_float4(x, y, z, x*x + y*y + z*z);
    }
    __syncthreads();

    const int lane = tid & 31;
    const int q    = blockIdx.x * 8 + (tid >> 5);
    const int row  = b * N2_ + q;

    const float qx = xyz2[row*3+0];
    const float qy = xyz2[row*3+1];
    const float qz = xyz2[row*3+2];
    const float q2 = qx*qx + qy*qy + qz*qz;
    const float ax = -2.f*qx, ay = -2.f*qy, az = -2.f*qz;

    // per-lane top-3 of d' (sorted ascending)
    float t0 = 3.4e38f, t1 = 3.4e38f, t2 = 3.4e38f;
    int   i0 = 0, i1 = 0, i2 = 0;

    #pragma unroll 8
    for (int i = lane; i < N1_; i += 32) {
        float4 p = sp[i];
        float d = fmaf(ax, p.x, fmaf(ay, p.y, fmaf(az, p.z, p.w)));
        if (d < t2) {
            if (d < t1) {
                t2 = t1; i2 = i1;
                if (d < t0) { t1 = t0; i1 = i0; t0 = d; i0 = i; }
                else        { t1 = d;  i1 = i; }
            } else { t2 = d; i2 = i; }
        }
    }

    // merge top-3 across the warp: 3 rounds of arg-min over each lane's head
    int head = 0;
    float selD[3]; int selI[3];
    #pragma unroll
    for (int r = 0; r < 3; ++r) {
        float cd  = (head == 0) ? t0 : (head == 1) ? t1 : (head == 2) ? t2 : 3.4e38f;
        int   ci  = (head == 0) ? i0 : (head == 1) ? i1 : (head == 2) ? i2 : 0;
        float bestD = cd; int bestLane = lane;
        #pragma unroll
        for (int off = 16; off; off >>= 1) {
            float od = __shfl_xor_sync(0xffffffffu, bestD, off);
            int   ol = __shfl_xor_sync(0xffffffffu, bestLane, off);
            if (od < bestD || (od == bestD && ol < bestLane)) { bestD = od; bestLane = ol; }
        }
        selD[r] = bestD;
        selI[r] = __shfl_sync(0xffffffffu, ci, bestLane);
        if (lane == bestLane) head++;
    }

    float d0 = fmaxf(selD[0] + q2, 1e-10f);
    float d1 = fmaxf(selD[1] + q2, 1e-10f);
    float d2 = fmaxf(selD[2] + q2, 1e-10f);
    float w0 = 1.f / (d0 + 1e-8f);
    float w1 = 1.f / (d1 + 1e-8f);
    float w2 = 1.f / (d2 + 1e-8f);
    float inv = 1.f / (w0 + w1 + w2);
    w0 *= inv; w1 *= inv; w2 *= inv;

    const float* p0 = pts1 + (size_t)(b * N1_ + selI[0]) * C1_;
    const float* p1 = pts1 + (size_t)(b * N1_ + selI[1]) * C1_;
    const float* p2 = pts1 + (size_t)(b * N1_ + selI[2]) * C1_;
    float* xr = g_X + (size_t)row * INCH;

    for (int c = lane; c < C1_; c += 32)
        xr[c] = w0 * p0[c] + w1 * p1[c] + w2 * p2[c];

    const float* pq = pts2 + (size_t)row * C2_;
    for (int c = lane; c < C2_; c += 32)
        xr[C1_ + c] = pq[c];
}

// ---------------------------------------------------------------------------
// tf32 tensor-core GEMM + fused BN(eval)+ReLU epilogue.
// C[M=32768, N=256] = relu(BN(A[M,K] @ W[K,256] + bias))
// 128x128 block tile, BK=16, 256 threads = 8 warps (2m x 4n), warp 64x32,
// mma.sync.m16n8k8 tf32 with fp32 accumulate. SMEM k-major, pad SPAD=136.
// ---------------------------------------------------------------------------
__device__ __forceinline__ uint32_t f2tf(float f) {
    uint32_t r;
    asm("cvt.rna.tf32.f32 %0, %1;" : "=r"(r) : "f"(f));
    return r;
}

__device__ __forceinline__ void mma_tf32(float c[4],
    uint32_t a0, uint32_t a1, uint32_t a2, uint32_t a3,
    uint32_t b0, uint32_t b1)
{
    asm volatile(
        "mma.sync.aligned.m16n8k8.row.col.f32.tf32.tf32.f32 "
        "{%0,%1,%2,%3}, {%4,%5,%6,%7}, {%8,%9}, {%0,%1,%2,%3};"
        : "+f"(c[0]), "+f"(c[1]), "+f"(c[2]), "+f"(c[3])
        : "r"(a0), "r"(a1), "r"(a2), "r"(a3), "r"(b0), "r"(b1));
}

template<int K>
__device__ __forceinline__ void gemm_tf32_body(
    const float* __restrict__ A, const float* __restrict__ W,
    const float* __restrict__ bias, const float* __restrict__ gamma,
    const float* __restrict__ beta, const float* __restrict__ rmean,
    const float* __restrict__ rvar, float* __restrict__ C)
{
    __shared__ uint32_t As[2][BKQ][SPAD];   // [k][m]
    __shared__ uint32_t Bs[2][BKQ][SPAD];   // [k][n]

    const int tid  = threadIdx.x;
    const int lane = tid & 31;
    const int warp = tid >> 5;
    const int wm   = warp & 1;        // 0..1 (m)
    const int wn   = warp >> 1;       // 0..3 (n)
    const int m0   = blockIdx.y * 128;
    const int n0   = blockIdx.x * 128;
    const int g4   = lane >> 2;       // 0..7
    const int c4   = lane & 3;        // 0..3

    // Loader mapping
    const int am = tid & 127;         // A: m row
    const int ac = tid >> 7;          // A: chunk 0/1  (k = ac*4 and ac*4+8)
    const int bk = tid >> 4;          // B: k row 0..15
    const int bc = tid & 15;          // B: float4 col (cols bc*4 and bc*4+64)

    const float* Ag = A + (size_t)(m0 + am) * K + ac * 4;
    const float* Bg = W + (size_t)bk * OUTCH + n0 + bc * 4;

    float acc[4][4][4];
    #pragma unroll
    for (int i = 0; i < 4; ++i)
        #pragma unroll
        for (int j = 0; j < 4; ++j)
            #pragma unroll
            for (int r = 0; r < 4; ++r) acc[i][j][r] = 0.f;

    constexpr int NK = K / BKQ;
    float4 av0, av1, bv0, bv1;

    // prologue: load + store stage 0
    av0 = *(const float4*)(Ag);
    av1 = *(const float4*)(Ag + 8);
    bv0 = *(const float4*)(Bg);
    bv1 = *(const float4*)(Bg + 64);
    {
        const int ka = ac * 4;
        As[0][ka+0][am] = f2tf(av0.x); As[0][ka+1][am] = f2tf(av0.y);
        As[0][ka+2][am] = f2tf(av0.z); As[0][ka+3][am] = f2tf(av0.w);
        As[0][ka+8][am] = f2tf(av1.x); As[0][ka+9][am] = f2tf(av1.y);
        As[0][ka+10][am] = f2tf(av1.z); As[0][ka+11][am] = f2tf(av1.w);
        uint4 t0 = make_uint4(f2tf(bv0.x), f2tf(bv0.y), f2tf(bv0.z), f2tf(bv0.w));
        uint4 t1 = make_uint4(f2tf(bv1.x), f2tf(bv1.y), f2tf(bv1.z), f2tf(bv1.w));
        *(uint4*)&Bs[0][bk][bc*4]      = t0;
        *(uint4*)&Bs[0][bk][64 + bc*4] = t1;
    }
    __syncthreads();

    #pragma unroll
    for (int kt = 0; kt < NK; ++kt) {
        const int buf = kt & 1;
        const bool pf = (kt + 1 < NK);
        if (pf) {
            av0 = *(const float4*)(Ag + (kt+1) * BKQ);
            av1 = *(const float4*)(Ag + (kt+1) * BKQ + 8);
            bv0 = *(const float4*)(Bg + (size_t)((kt+1) * BKQ) * OUTCH);
            bv1 = *(const float4*)(Bg + (size_t)((kt+1) * BKQ) * OUTCH + 64);
        }

        #pragma unroll
        for (int kf = 0; kf < 2; ++kf) {
            const int kr = kf * 8 + c4;
            uint32_t a[4][4], bfrag[4][2];
            #pragma unroll
            for (int i = 0; i < 4; ++i) {
                const int r = wm * 64 + i * 16 + g4;
                a[i][0] = As[buf][kr  ][r];
                a[i][1] = As[buf][kr  ][r + 8];
                a[i][2] = As[buf][kr+4][r];
                a[i][3] = As[buf][kr+4][r + 8];
            }
            #pragma unroll
            for (int j = 0; j < 4; ++j) {
                const int cc = wn * 32 + j * 8 + g4;
                bfrag[j][0] = Bs[buf][kr  ][cc];
                bfrag[j][1] = Bs[buf][kr+4][cc];
            }
            #pragma unroll
            for (int i = 0; i < 4; ++i)
                #pragma unroll
                for (int j = 0; j < 4; ++j)
                    mma_tf32(acc[i][j], a[i][0], a[i][1], a[i][2], a[i][3],
                             bfrag[j][0], bfrag[j][1]);
        }

        if (pf) {
            const int nb = buf ^ 1;
            const int ka = ac * 4;
            As[nb][ka+0][am] = f2tf(av0.x); As[nb][ka+1][am] = f2tf(av0.y);
            As[nb][ka+2][am] = f2tf(av0.z); As[nb][ka+3][am] = f2tf(av0.w);
            As[nb][ka+8][am] = f2tf(av1.x); As[nb][ka+9][am] = f2tf(av1.y);
            As[nb][ka+10][am] = f2tf(av1.z); As[nb][ka+11][am] = f2tf(av1.w);
            uint4 t0 = make_uint4(f2tf(bv0.x), f2tf(bv0.y), f2tf(bv0.z), f2tf(bv0.w));
            uint4 t1 = make_uint4(f2tf(bv1.x), f2tf(bv1.y), f2tf(bv1.z), f2tf(bv1.w));
            *(uint4*)&Bs[nb][bk][bc*4]      = t0;
            *(uint4*)&Bs[nb][bk][64 + bc*4] = t1;
        }
        __syncthreads();
    }

    // Epilogue: per-thread columns are j*8 + 2*c4 + {0,1}, j = 0..3
    float sc[4][2], sh[4][2];
    #pragma unroll
    for (int j = 0; j < 4; ++j) {
        #pragma unroll
        for (int e = 0; e < 2; ++e) {
            const int col = n0 + wn * 32 + j * 8 + 2 * c4 + e;
            const float s = gamma[col] * rsqrtf(rvar[col] + 1e-5f);
            sc[j][e] = s;
            sh[j][e] = (bias[col] - rmean[col]) * s + beta[col];
        }
    }
    #pragma unroll
    for (int i = 0; i < 4; ++i) {
        const int r0 = m0 + wm * 64 + i * 16 + g4;
        #pragma unroll
        for (int j = 0; j < 4; ++j) {
            const int cb = n0 + wn * 32 + j * 8 + 2 * c4;
            float2 v0, v1;
            v0.x = fmaxf(acc[i][j][0] * sc[j][0] + sh[j][0], 0.f);
            v0.y = fmaxf(acc[i][j][1] * sc[j][1] + sh[j][1], 0.f);
            v1.x = fmaxf(acc[i][j][2] * sc[j][0] + sh[j][0], 0.f);
            v1.y = fmaxf(acc[i][j][3] * sc[j][1] + sh[j][1], 0.f);
            *(float2*)(C + (size_t)r0 * OUTCH + cb)       = v0;
            *(float2*)(C + (size_t)(r0 + 8) * OUTCH + cb) = v1;
        }
    }
}

__global__ __launch_bounds__(256, 2) void gemm1_tf32(
    const float* __restrict__ W, const float* __restrict__ bias,
    const float* __restrict__ gamma, const float* __restrict__ beta,
    const float* __restrict__ rmean, const float* __restrict__ rvar)
{
    gemm_tf32_body<INCH>(g_X, W, bias, gamma, beta, rmean, rvar, g_Y1);
}

__global__ __launch_bounds__(256, 2) void gemm2_tf32(
    const float* __restrict__ W, const float* __restrict__ bias,
    const float* __restrict__ gamma, const float* __restrict__ beta,
    const float* __restrict__ rmean, const float* __restrict__ rvar,
    float* __restrict__ C)
{
    gemm_tf32_body<OUTCH>(g_Y1, W, bias, gamma, beta, rmean, rvar, C);
}

// ---------------------------------------------------------------------------
extern "C" void kernel_launch(void* const* d_in, const int* in_sizes, int n_in,
                              void* d_out, int out_size)
{
    const float* xyz1 = (const float*)d_in[0];
    const float* xyz2 = (const float*)d_in[1];
    const float* pts1 = (const float*)d_in[2];
    const float* pts2 = (const float*)d_in[3];
    const float* W1   = (const float*)d_in[4];
    const float* b1   = (const float*)d_in[5];
    const float* g1   = (const float*)d_in[6];
    const float* be1  = (const float*)d_in[7];
    const float* rm1  = (const float*)d_in[8];
    const float* rv1  = (const float*)d_in[9];
    const float* W2   = (const float*)d_in[10];
    const float* b2   = (const float*)d_in[11];
    const float* g2   = (const float*)d_in[12];
    const float* be2  = (const float*)d_in[13];
    const float* rm2  = (const float*)d_in[14];
    const float* rv2  = (const float*)d_in[15];
    float* out = (float*)d_out;

    knn_interp_kernel<<<dim3(N2_ / 8, B_), 256>>>(xyz1, xyz2, pts1, pts2);
    gemm1_tf32<<<dim3(OUTCH / 128, (B_ * N2_) / 128), 256>>>(W1, b1, g1, be1, rm1, rv1);
    gemm2_tf32<<<dim3(OUTCH / 128, (B_ * N2_) / 128), 256>>>(W2, b2, g2, be2, rm2, rv2, out);
}

// round 5
// speedup vs baseline: 1.8576x; 1.2071x over previous
#include <cuda_runtime.h>
#include <cstdint>

#define B_    4
#define N1_   2048
#define N2_   8192
#define C1_   256
#define C2_   128
#define INCH  384
#define OUTCH 256
#define BKQ   16
#define ASTR  20      // A smem row stride (floats): conflict-free frag loads
#define BSTR  136     // B smem row stride (floats): conflict-free frag loads
#define STAGES 4
#define A_STG (128 * ASTR)          // 2560 floats / stage
#define B_STG (BKQ * BSTR)          // 2176 floats / stage
#define DYN_SMEM ((STAGES * (A_STG + B_STG)) * 4)   // 75776 bytes

// Scratch (__device__ globals per allocation-free rule)
__device__ float g_X [B_ * N2_ * INCH];    // tf32-rounded concat input
__device__ float g_Y1[B_ * N2_ * OUTCH];   // tf32-rounded layer-1 output
__device__ float g_W1[INCH  * OUTCH];      // tf32-rounded weights
__device__ float g_W2[OUTCH * OUTCH];

__device__ __forceinline__ float f2tf_f(float f) {
    uint32_t r;
    asm("cvt.rna.tf32.f32 %0, %1;" : "=r"(r) : "f"(f));
    return __uint_as_float(r);
}

// ---------------------------------------------------------------------------
// Kernel 0: round weights to tf32 once
// ---------------------------------------------------------------------------
__global__ void round_weights(const float* __restrict__ W1,
                              const float* __restrict__ W2)
{
    const int i = blockIdx.x * 256 + threadIdx.x;
    const int n1 = INCH * OUTCH, n2 = OUTCH * OUTCH;
    for (int k = i; k < n1; k += gridDim.x * 256) g_W1[k] = f2tf_f(W1[k]);
    for (int k = i; k < n2; k += gridDim.x * 256) g_W2[k] = f2tf_f(W2[k]);
}

// ---------------------------------------------------------------------------
// Kernel 1: KNN (K=3) + inverse-distance interp + concat -> g_X (tf32-rounded)
// Exact fp32 distance compares (selection must match reference).
// ---------------------------------------------------------------------------
__global__ __launch_bounds__(256) void knn_interp_kernel(
    const float* __restrict__ xyz1, const float* __restrict__ xyz2,
    const float* __restrict__ pts1, const float* __restrict__ pts2)
{
    __shared__ float4 sp[N1_];
    const int b   = blockIdx.y;
    const int tid = threadIdx.x;

    const float* x1 = xyz1 + (size_t)b * N1_ * 3;
    for (int p = tid; p < N1_; p += 256) {
        float x = x1[3*p], y = x1[3*p+1], z = x1[3*p+2];
        sp[p] = make_float4(x, y, z, x*x + y*y + z*z);
    }
    __syncthreads();

    const int lane = tid & 31;
    const int q    = blockIdx.x * 8 + (tid >> 5);
    const int row  = b * N2_ + q;

    const float qx = xyz2[row*3+0];
    const float qy = xyz2[row*3+1];
    const float qz = xyz2[row*3+2];
    const float q2 = qx*qx + qy*qy + qz*qz;
    const float ax = -2.f*qx, ay = -2.f*qy, az = -2.f*qz;

    float t0 = 3.4e38f, t1 = 3.4e38f, t2 = 3.4e38f;
    int   i0 = 0, i1 = 0, i2 = 0;

    #pragma unroll 8
    for (int i = lane; i < N1_; i += 32) {
        float4 p = sp[i];
        float d = fmaf(ax, p.x, fmaf(ay, p.y, fmaf(az, p.z, p.w)));
        if (d < t2) {
            if (d < t1) {
                t2 = t1; i2 = i1;
                if (d < t0) { t1 = t0; i1 = i0; t0 = d; i0 = i; }
                else        { t1 = d;  i1 = i; }
            } else { t2 = d; i2 = i; }
        }
    }

    int head = 0;
    float selD[3]; int selI[3];
    #pragma unroll
    for (int r = 0; r < 3; ++r) {
        float cd  = (head == 0) ? t0 : (head == 1) ? t1 : (head == 2) ? t2 : 3.4e38f;
        int   ci  = (head == 0) ? i0 : (head == 1) ? i1 : (head == 2) ? i2 : 0;
        float bestD = cd; int bestLane = lane;
        #pragma unroll
        for (int off = 16; off; off >>= 1) {
            float od = __shfl_xor_sync(0xffffffffu, bestD, off);
            int   ol = __shfl_xor_sync(0xffffffffu, bestLane, off);
            if (od < bestD || (od == bestD && ol < bestLane)) { bestD = od; bestLane = ol; }
        }
        selD[r] = bestD;
        selI[r] = __shfl_sync(0xffffffffu, ci, bestLane);
        if (lane == bestLane) head++;
    }

    float d0 = fmaxf(selD[0] + q2, 1e-10f);
    float d1 = fmaxf(selD[1] + q2, 1e-10f);
    float d2 = fmaxf(selD[2] + q2, 1e-10f);
    float w0 = 1.f / (d0 + 1e-8f);
    float w1 = 1.f / (d1 + 1e-8f);
    float w2 = 1.f / (d2 + 1e-8f);
    float inv = 1.f / (w0 + w1 + w2);
    w0 *= inv; w1 *= inv; w2 *= inv;

    const float* p0 = pts1 + (size_t)(b * N1_ + selI[0]) * C1_;
    const float* p1 = pts1 + (size_t)(b * N1_ + selI[1]) * C1_;
    const float* p2 = pts1 + (size_t)(b * N1_ + selI[2]) * C1_;
    float* xr = g_X + (size_t)row * INCH;

    // 8 consecutive channels per lane, float4-vectorized, tf32-rounded on store
    const int c8 = lane * 8;
    #pragma unroll
    for (int h = 0; h < 2; ++h) {
        float4 a = *(const float4*)(p0 + c8 + h*4);
        float4 bb = *(const float4*)(p1 + c8 + h*4);
        float4 c = *(const float4*)(p2 + c8 + h*4);
        float4 o;
        o.x = f2tf_f(w0*a.x + w1*bb.x + w2*c.x);
        o.y = f2tf_f(w0*a.y + w1*bb.y + w2*c.y);
        o.z = f2tf_f(w0*a.z + w1*bb.z + w2*c.z);
        o.w = f2tf_f(w0*a.w + w1*bb.w + w2*c.w);
        *(float4*)(xr + c8 + h*4) = o;
    }
    // pts2 copy: 4 channels per lane
    {
        const float* pq = pts2 + (size_t)row * C2_;
        float4 v = *(const float4*)(pq + lane * 4);
        v.x = f2tf_f(v.x); v.y = f2tf_f(v.y); v.z = f2tf_f(v.z); v.w = f2tf_f(v.w);
        *(float4*)(xr + C1_ + lane * 4) = v;
    }
}

// ---------------------------------------------------------------------------
// tf32 tensor-core GEMM, 4-stage cp.async pipeline, fused BN+ReLU epilogue.
// Inputs pre-rounded to tf32 bit patterns -> zero CVT in mainloop.
// 128x128 tile, BK=16, 8 warps (2m x 4n), warp 64x32, mma.m16n8k8.
// ---------------------------------------------------------------------------
__device__ __forceinline__ void cp16(void* dst, const void* src) {
    uint32_t d = (uint32_t)__cvta_generic_to_shared(dst);
    asm volatile("cp.async.cg.shared.global [%0], [%1], 16;\n" :: "r"(d), "l"(src));
}
__device__ __forceinline__ void cp_commit() {
    asm volatile("cp.async.commit_group;\n");
}
__device__ __forceinline__ void cp_wait2() {
    asm volatile("cp.async.wait_group 2;\n");
}

__device__ __forceinline__ void mma_tf32(float c[4],
    uint32_t a0, uint32_t a1, uint32_t a2, uint32_t a3,
    uint32_t b0, uint32_t b1)
{
    asm volatile(
        "mma.sync.aligned.m16n8k8.row.col.f32.tf32.tf32.f32 "
        "{%0,%1,%2,%3}, {%4,%5,%6,%7}, {%8,%9}, {%0,%1,%2,%3};"
        : "+f"(c[0]), "+f"(c[1]), "+f"(c[2]), "+f"(c[3])
        : "r"(a0), "r"(a1), "r"(a2), "r"(a3), "r"(b0), "r"(b1));
}

template<int K, bool ROUND_OUT>
__device__ __forceinline__ void gemm_body(
    const float* __restrict__ A, const float* __restrict__ W,
    const float* __restrict__ bias, const float* __restrict__ gamma,
    const float* __restrict__ beta, const float* __restrict__ rmean,
    const float* __restrict__ rvar, float* __restrict__ C)
{
    extern __shared__ float sm[];
    float* sA = sm;                       // STAGES * A_STG
    float* sB = sm + STAGES * A_STG;      // STAGES * B_STG

    const int tid  = threadIdx.x;
    const int lane = tid & 31;
    const int warp = tid >> 5;
    const int wm   = warp & 1;
    const int wn   = warp >> 1;
    const int m0   = blockIdx.y * 128;
    const int n0   = blockIdx.x * 128;
    const int g4   = lane >> 2;
    const int c4   = lane & 3;

    // Loader mapping: A) m = tid>>1, k-half = tid&1 (8 floats = 2x16B)
    //                 B) kr = tid>>4, 8 n-floats at (tid&15)*8
    const int m_ld  = tid >> 1;
    const int half  = (tid & 1) * 8;
    const int kr_ld = tid >> 4;
    const int nc8   = (tid & 15) * 8;

    const float* Agp = A + (size_t)(m0 + m_ld) * K + half;
    const float* Bgp = W + (size_t)kr_ld * OUTCH + n0 + nc8;
    float* sAme = sA + m_ld * ASTR + half;
    float* sBme = sB + kr_ld * BSTR + nc8;

    constexpr int NK = K / BKQ;

    float acc[4][4][4];
    #pragma unroll
    for (int i = 0; i < 4; ++i)
        #pragma unroll
        for (int j = 0; j < 4; ++j)
            #pragma unroll
            for (int r = 0; r < 4; ++r) acc[i][j][r] = 0.f;

    // Prologue: issue stages 0..2
    #pragma unroll
    for (int p = 0; p < STAGES - 1; ++p) {
        cp16(sAme + p * A_STG,     Agp + p * BKQ);
        cp16(sAme + p * A_STG + 4, Agp + p * BKQ + 4);
        cp16(sBme + p * B_STG,     Bgp + (size_t)p * BKQ * OUTCH);
        cp16(sBme + p * B_STG + 4, Bgp + (size_t)p * BKQ * OUTCH + 4);
        cp_commit();
    }

    for (int kt = 0; kt < NK; ++kt) {
        cp_wait2();          // stage kt resident
        __syncthreads();     // all warps done with stage (kt-1)

        const int nxt = kt + STAGES - 1;
        if (nxt < NK) {
            const int st = nxt & (STAGES - 1);
            cp16(sAme + st * A_STG,     Agp + nxt * BKQ);
            cp16(sAme + st * A_STG + 4, Agp + nxt * BKQ + 4);
            cp16(sBme + st * B_STG,     Bgp + (size_t)nxt * BKQ * OUTCH);
            cp16(sBme + st * B_STG + 4, Bgp + (size_t)nxt * BKQ * OUTCH + 4);
        }
        cp_commit();         // empty group when nothing issued (keeps counts aligned)

        const float* cA = sA + (kt & (STAGES - 1)) * A_STG;
        const float* cB = sB + (kt & (STAGES - 1)) * B_STG;

        #pragma unroll
        for (int kf = 0; kf < 2; ++kf) {
            const int kr = kf * 8 + c4;
            uint32_t a[4][4], bf[4][2];
            #pragma unroll
            for (int i = 0; i < 4; ++i) {
                const int r = wm * 64 + i * 16 + g4;
                a[i][0] = __float_as_uint(cA[r * ASTR + kr]);
                a[i][1] = __float_as_uint(cA[(r + 8) * ASTR + kr]);
                a[i][2] = __float_as_uint(cA[r * ASTR + kr + 4]);
                a[i][3] = __float_as_uint(cA[(r + 8) * ASTR + kr + 4]);
            }
            #pragma unroll
            for (int j = 0; j < 4; ++j) {
                const int cc = wn * 32 + j * 8 + g4;
                bf[j][0] = __float_as_uint(cB[kr * BSTR + cc]);
                bf[j][1] = __float_as_uint(cB[(kr + 4) * BSTR + cc]);
            }
            #pragma unroll
            for (int i = 0; i < 4; ++i)
                #pragma unroll
                for (int j = 0; j < 4; ++j)
                    mma_tf32(acc[i][j], a[i][0], a[i][1], a[i][2], a[i][3],
                             bf[j][0], bf[j][1]);
        }
    }

    // Fused BN+ReLU epilogue; optional tf32 rounding of outputs
    float sc[4][2], sh[4][2];
    #pragma unroll
    for (int j = 0; j < 4; ++j) {
        #pragma unroll
        for (int e = 0; e < 2; ++e) {
            const int col = n0 + wn * 32 + j * 8 + 2 * c4 + e;
            const float s = gamma[col] * rsqrtf(rvar[col] + 1e-5f);
            sc[j][e] = s;
            sh[j][e] = (bias[col] - rmean[col]) * s + beta[col];
        }
    }
    #pragma unroll
    for (int i = 0; i < 4; ++i) {
        const int r0 = m0 + wm * 64 + i * 16 + g4;
        #pragma unroll
        for (int j = 0; j < 4; ++j) {
            const int cb = n0 + wn * 32 + j * 8 + 2 * c4;
            float2 v0, v1;
            v0.x = fmaxf(acc[i][j][0] * sc[j][0] + sh[j][0], 0.f);
            v0.y = fmaxf(acc[i][j][1] * sc[j][1] + sh[j][1], 0.f);
            v1.x = fmaxf(acc[i][j][2] * sc[j][0] + sh[j][0], 0.f);
            v1.y = fmaxf(acc[i][j][3] * sc[j][1] + sh[j][1], 0.f);
            if (ROUND_OUT) {
                v0.x = f2tf_f(v0.x); v0.y = f2tf_f(v0.y);
                v1.x = f2tf_f(v1.x); v1.y = f2tf_f(v1.y);
            }
            *(float2*)(C + (size_t)r0 * OUTCH + cb)       = v0;
            *(float2*)(C + (size_t)(r0 + 8) * OUTCH + cb) = v1;
        }
    }
}

__global__ __launch_bounds__(256, 2) void gemm1_tf32(
    const float* __restrict__ bias, const float* __restrict__ gamma,
    const float* __restrict__ beta, const float* __restrict__ rmean,
    const float* __restrict__ rvar)
{
    gemm_body<INCH, true>(g_X, g_W1, bias, gamma, beta, rmean, rvar, g_Y1);
}

__global__ __launch_bounds__(256, 2) void gemm2_tf32(
    const float* __restrict__ bias, const float* __restrict__ gamma,
    const float* __restrict__ beta, const float* __restrict__ rmean,
    const float* __restrict__ rvar, float* __restrict__ C)
{
    gemm_body<OUTCH, false>(g_Y1, g_W2, bias, gamma, beta, rmean, rvar, C);
}

// ---------------------------------------------------------------------------
extern "C" void kernel_launch(void* const* d_in, const int* in_sizes, int n_in,
                              void* d_out, int out_size)
{
    const float* xyz1 = (const float*)d_in[0];
    const float* xyz2 = (const float*)d_in[1];
    const float* pts1 = (const float*)d_in[2];
    const float* pts2 = (const float*)d_in[3];
    const float* W1   = (const float*)d_in[4];
    const float* b1   = (const float*)d_in[5];
    const float* g1   = (const float*)d_in[6];
    const float* be1  = (const float*)d_in[7];
    const float* rm1  = (const float*)d_in[8];
    const float* rv1  = (const float*)d_in[9];
    const float* W2   = (const float*)d_in[10];
    const float* b2   = (const float*)d_in[11];
    const float* g2   = (const float*)d_in[12];
    const float* be2  = (const float*)d_in[13];
    const float* rm2  = (const float*)d_in[14];
    const float* rv2  = (const float*)d_in[15];
    float* out = (float*)d_out;

    static bool attr_set = false;
    if (!attr_set) {
        cudaFuncSetAttribute(gemm1_tf32,
            cudaFuncAttributeMaxDynamicSharedMemorySize, DYN_SMEM);
        cudaFuncSetAttribute(gemm2_tf32,
            cudaFuncAttributeMaxDynamicSharedMemorySize, DYN_SMEM);
        attr_set = true;
    }

    round_weights<<<64, 256>>>(W1, W2);
    knn_interp_kernel<<<dim3(N2_ / 8, B_), 256>>>(xyz1, xyz2, pts1, pts2);
    gemm1_tf32<<<dim3(OUTCH / 128, (B_ * N2_) / 128), 256, DYN_SMEM>>>(b1, g1, be1, rm1, rv1);
    gemm2_tf32<<<dim3(OUTCH / 128, (B_ * N2_) / 128), 256, DYN_SMEM>>>(b2, g2, be2, rm2, rv2, out);
}